// round 13
// baseline (speedup 1.0000x reference)
#include <cuda_runtime.h>
#include <math.h>

#define NN   100000
#define EE   1600000
#define ET   (EE + NN)     // edges + self loops
#define FIN  128
#define DD   64
#define HH   8
#define GG   64
#define NCLS 10
#define SLOPE 0.2f

#define SCAT_BLOCKS ((ET + 255) / 256)   // 6641

// ---------------- scratch (device globals) ----------------
__device__ float g_proj[NN * DD];        // h = I @ W (fp32)
__device__ float g_act [NN * DD];        // normalized layer output
__device__ float g_als [NN * HH];
__device__ float g_ald [NN * HH];
__device__ int   g_rowptr[NN + 1];
__device__ int   g_col [ET];
__device__ int   g_cnti[NN];             // zero-init; re-zeroed by scatter tail
__device__ int   g_rank[ET];
__device__ float g_sums[GG * DD];        // zero-init; re-zeroed by final tail
__device__ float g_cnt [GG];

// ---------------- CSR build ----------------
__global__ void hist_kernel(const int* __restrict__ ei) {
    int i = blockIdx.x * blockDim.x + threadIdx.x;
    if (i >= ET) return;
    int dst = (i < EE) ? ei[EE + i] : (i - EE);
    g_rank[i] = atomicAdd(&g_cnti[dst], 1);
}

// Single-block fused exclusive scan of g_cnti -> g_rowptr.
__global__ void scanF_kernel() {
    __shared__ int wsum[32];
    __shared__ int woff[32];
    __shared__ int tot;
    const int t = threadIdx.x;
    const int lane = t & 31, wid = t >> 5;
    int run = 0;
    for (int chunk = 0; chunk < 98; chunk++) {
        int idx = chunk * 1024 + t;
        int v = (idx < NN) ? g_cnti[idx] : 0;
        int inc = v;
#pragma unroll
        for (int off = 1; off < 32; off <<= 1) {
            int x = __shfl_up_sync(0xffffffffu, inc, off);
            if (lane >= off) inc += x;
        }
        if (lane == 31) wsum[wid] = inc;
        __syncthreads();
        if (wid == 0) {
            int s = wsum[lane];
            int is = s;
#pragma unroll
            for (int off = 1; off < 32; off <<= 1) {
                int x = __shfl_up_sync(0xffffffffu, is, off);
                if (lane >= off) is += x;
            }
            woff[lane] = is - s;
            if (lane == 31) tot = is;
        }
        __syncthreads();
        if (idx < NN) g_rowptr[idx] = run + woff[wid] + (inc - v);
        run += tot;
    }
    if (t == 0) g_rowptr[NN] = run;
}

// ---------------- GEMM body: 64x64 tile, 4x4/thread, k-major xs -------------
// xs_t[k][node] pad 76: 304B row stride (16B-aligned -> LDS.128 legal),
// 12-bank rotation (<=2-way staging conflicts). Inner loop: 2 LDS.128 / 16 FMA.
template<int K, bool FIRST>
__device__ __forceinline__ void gemm_body(int bid,
                                          const float* __restrict__ I,
                                          const float* __restrict__ W,
                                          const float* __restrict__ a_src,
                                          const float* __restrict__ a_dst,
                                          const float* __restrict__ prev_bias) {
    __shared__ float xs_t[64][76];
    __shared__ float Wsm[64][64];
    const int t  = threadIdx.x;
    const int tx = t & 15;
    const int ty = t >> 4;
    const int node0 = bid * 64;

    float acc[4][4];
#pragma unroll
    for (int i = 0; i < 4; i++)
#pragma unroll
        for (int j = 0; j < 4; j++) acc[i][j] = 0.f;

    for (int kc = 0; kc < K; kc += 64) {
        // stage xs transposed: 64 nodes x 64 k (1024 float4 reads, 4/thread)
#pragma unroll
        for (int it = 0; it < 4; it++) {
            int fid  = t + it * 256;
            int node = fid >> 4;
            int kq   = (fid & 15) * 4;
            int gn   = node0 + node;
            float4 v = make_float4(0.f, 0.f, 0.f, 0.f);
            if (gn < NN) {
                if (FIRST) {
                    v = *(const float4*)&I[(size_t)gn * K + kc + kq];
                } else {
                    v = *(const float4*)&g_act[(size_t)gn * K + kc + kq];
                    v.x += prev_bias[kc + kq    ];
                    v.y += prev_bias[kc + kq + 1];
                    v.z += prev_bias[kc + kq + 2];
                    v.w += prev_bias[kc + kq + 3];
                    v.x = v.x > 0.f ? v.x : expm1f(v.x);
                    v.y = v.y > 0.f ? v.y : expm1f(v.y);
                    v.z = v.z > 0.f ? v.z : expm1f(v.z);
                    v.w = v.w > 0.f ? v.w : expm1f(v.w);
                }
            }
            xs_t[kq    ][node] = v.x;
            xs_t[kq + 1][node] = v.y;
            xs_t[kq + 2][node] = v.z;
            xs_t[kq + 3][node] = v.w;
        }
        // stage W chunk: 64 x 64 (1024 float4, 4/thread)
#pragma unroll
        for (int it = 0; it < 4; it++) {
            int fid = t + it * 256;
            int kk  = fid >> 4;
            int cq  = (fid & 15) * 4;
            *(float4*)&Wsm[kk][cq] = *(const float4*)&W[(size_t)(kc + kk) * DD + cq];
        }
        __syncthreads();
#pragma unroll
        for (int k = 0; k < 64; k++) {
            float4 wv = *(const float4*)&Wsm[k][tx * 4];
            float4 xv = *(const float4*)&xs_t[k][4 * ty];
            acc[0][0] = fmaf(xv.x, wv.x, acc[0][0]);
            acc[0][1] = fmaf(xv.x, wv.y, acc[0][1]);
            acc[0][2] = fmaf(xv.x, wv.z, acc[0][2]);
            acc[0][3] = fmaf(xv.x, wv.w, acc[0][3]);
            acc[1][0] = fmaf(xv.y, wv.x, acc[1][0]);
            acc[1][1] = fmaf(xv.y, wv.y, acc[1][1]);
            acc[1][2] = fmaf(xv.y, wv.z, acc[1][2]);
            acc[1][3] = fmaf(xv.y, wv.w, acc[1][3]);
            acc[2][0] = fmaf(xv.z, wv.x, acc[2][0]);
            acc[2][1] = fmaf(xv.z, wv.y, acc[2][1]);
            acc[2][2] = fmaf(xv.z, wv.z, acc[2][2]);
            acc[2][3] = fmaf(xv.z, wv.w, acc[2][3]);
            acc[3][0] = fmaf(xv.w, wv.x, acc[3][0]);
            acc[3][1] = fmaf(xv.w, wv.y, acc[3][1]);
            acc[3][2] = fmaf(xv.w, wv.z, acc[3][2]);
            acc[3][3] = fmaf(xv.w, wv.w, acc[3][3]);
        }
        __syncthreads();
    }

#pragma unroll
    for (int i = 0; i < 4; i++) {
        int gn = node0 + 4 * ty + i;
        if (gn < NN)
            *(float4*)&g_proj[(size_t)gn * DD + tx * 4] =
                make_float4(acc[i][0], acc[i][1], acc[i][2], acc[i][3]);
    }

    // attention logits: head tx>>1 (cols 8h..8h+7 split across tx, tx^1)
#pragma unroll
    for (int i = 0; i < 4; i++) {
        float s = 0.f, d = 0.f;
#pragma unroll
        for (int j = 0; j < 4; j++) {
            int c = tx * 4 + j;
            s = fmaf(acc[i][j], a_src[c], s);
            d = fmaf(acc[i][j], a_dst[c], d);
        }
        s += __shfl_xor_sync(0xffffffffu, s, 1);
        d += __shfl_xor_sync(0xffffffffu, d, 1);
        int gn = node0 + 4 * ty + i;
        if ((tx & 1) == 0 && gn < NN) {
            int h = tx >> 1;
            g_als[gn * HH + h] = s;
            g_ald[gn * HH + h] = d;
        }
    }
}

// ---------------- fused scatter + layer-1 GEMM ------------------------------
__global__ void scatter_gemm1_kernel(const int* __restrict__ ei,
                                     const float* __restrict__ x,
                                     const float* __restrict__ W1,
                                     const float* __restrict__ a1s,
                                     const float* __restrict__ a1d) {
    if (blockIdx.x < SCAT_BLOCKS) {
        int i = blockIdx.x * 256 + threadIdx.x;
        if (i < NN) g_cnti[i] = 0;
        if (i >= ET) return;
        int src, dst;
        if (i < EE) { src = ei[i]; dst = ei[EE + i]; }
        else        { src = dst = i - EE; }
        g_col[g_rowptr[dst] + g_rank[i]] = src;
    } else {
        gemm_body<FIN, true>(blockIdx.x - SCAT_BLOCKS, x, W1, a1s, a1d, nullptr);
    }
}

// ---------------- standalone GEMM (layers 2/3) ------------------------------
template<int K>
__global__ void gemm_al_kernel(const float* __restrict__ W,
                               const float* __restrict__ a_src,
                               const float* __restrict__ a_dst,
                               const float* __restrict__ prev_bias) {
    gemm_body<K, false>(blockIdx.x, nullptr, W, a_src, a_dst, prev_bias);
}

// ---------------- dual-dst CSR edge kernel (128-thread blocks) --------------
#define EW 4
__global__ void __launch_bounds__(128) edge_csr_kernel() {
    __shared__ int   ss[EW][2][16];
    __shared__ float ws[EW][2][16][9];
    const int wl   = threadIdx.x >> 5;
    const int lane = threadIdx.x & 31;
    const int half = lane >> 4;
    const int l    = lane & 15;
    const int hh   = l >> 1;
    const int n = blockIdx.x * (2 * EW) + 2 * wl + half;   // NN%8==0: valid

    const int rs = g_rowptr[n], re = g_rowptr[n + 1];
    const int len  = re - rs;
    const int olen = __shfl_xor_sync(0xffffffffu, len, 16);
    const int mlen = max(len, olen);

    const float4 ad0 = *(const float4*)&g_ald[n * HH];
    const float4 ad1 = *(const float4*)&g_ald[n * HH + 4];

    float4 acc = make_float4(0.f, 0.f, 0.f, 0.f);
    float dn = 0.f;

    for (int base = 0; base < mlen; base += 16) {
        const int e = rs + base + l;
        const bool valid = (e < re);
        int src = valid ? g_col[e] : 0;
        ss[wl][half][l] = src;
        {
            float4 s0 = *(const float4*)&g_als[src * HH];
            float4 s1 = *(const float4*)&g_als[src * HH + 4];
            float ev[8] = { s0.x + ad0.x, s0.y + ad0.y, s0.z + ad0.z, s0.w + ad0.w,
                            s1.x + ad1.x, s1.y + ad1.y, s1.z + ad1.z, s1.w + ad1.w };
            const float m = valid ? 1.f : 0.f;
#pragma unroll
            for (int k = 0; k < 8; k++) {
                float v = ev[k] > 0.f ? ev[k] : SLOPE * ev[k];
                ws[wl][half][l][k] = m * __expf(v);
            }
        }
        __syncwarp();
        const int cnt = min(16, mlen - base);
#pragma unroll 4
        for (int j = 0; j < cnt; j++) {
            int   sj = ss[wl][half][j];
            float wj = ws[wl][half][j][hh];
            dn += wj;
            float4 p = *(const float4*)&g_proj[(size_t)sj * DD + 4 * l];
            acc.x = fmaf(p.x, wj, acc.x);
            acc.y = fmaf(p.y, wj, acc.y);
            acc.z = fmaf(p.z, wj, acc.z);
            acc.w = fmaf(p.w, wj, acc.w);
        }
        __syncwarp();
    }
    const float inv = 1.f / dn;
    *(float4*)&g_act[(size_t)n * DD + 4 * l] =
        make_float4(acc.x * inv, acc.y * inv, acc.z * inv, acc.w * inv);
}

// ---------------- hierarchical pool (flush-on-graph-change) ----------------
__global__ void pool2_kernel(const int* __restrict__ batch,
                             const float* __restrict__ b3) {
    const int t = threadIdx.x;          // 256
    const int d = t & 63;
    const int r = t >> 6;
    const int start = blockIdx.x * 256;
    const float bias = b3[d];
    int curg = -1;
    float accv = 0.f, accc = 0.f;
    for (int k = 0; k < 64; k++) {
        int n = start + r + k * 4;
        if (n >= NN) break;
        int g = batch[n];
        if (g != curg) {
            if (curg >= 0) {
                atomicAdd(&g_sums[curg * DD + d], accv);
                if (d == 0) atomicAdd(&g_cnt[curg], accc);
            }
            curg = g; accv = 0.f; accc = 0.f;
        }
        float v = g_act[(size_t)n * DD + d] + bias;
        v = v > 0.f ? v : expm1f(v);
        accv += v;
        accc += 1.f;
    }
    if (curg >= 0) {
        atomicAdd(&g_sums[curg * DD + d], accv);
        if (d == 0) atomicAdd(&g_cnt[curg], accc);
    }
}

// ---------------- final linear (+ re-zero pool buffers) ---------------------
__global__ void final_kernel(const float* __restrict__ lin_W,
                             const float* __restrict__ lin_b,
                             float* __restrict__ out) {
    int t = threadIdx.x;                // 640
    int g = t / NCLS;
    int c = t % NCLS;
    float cnt = fmaxf(g_cnt[g], 1.0f);
    float acc = lin_b[c];
#pragma unroll
    for (int d = 0; d < DD; d++)
        acc = fmaf(g_sums[g * DD + d] / cnt, lin_W[d * NCLS + c], acc);
    out[g * NCLS + c] = acc;
    __syncthreads();
    for (int i = t; i < GG * DD; i += 640) g_sums[i] = 0.f;
    if (t < GG) g_cnt[t] = 0.f;
}

// ---------------- launch ----------------
extern "C" void kernel_launch(void* const* d_in, const int* in_sizes, int n_in,
                              void* d_out, int out_size) {
    const float* x      = (const float*)d_in[0];
    const int*   ei     = (const int*)  d_in[1];
    const int*   batch  = (const int*)  d_in[2];
    const float* W1     = (const float*)d_in[3];
    const float* a1s    = (const float*)d_in[4];
    const float* a1d    = (const float*)d_in[5];
    const float* b1     = (const float*)d_in[6];
    const float* W2     = (const float*)d_in[7];
    const float* a2s    = (const float*)d_in[8];
    const float* a2d    = (const float*)d_in[9];
    const float* b2     = (const float*)d_in[10];
    const float* W3     = (const float*)d_in[11];
    const float* a3s    = (const float*)d_in[12];
    const float* a3d    = (const float*)d_in[13];
    const float* b3     = (const float*)d_in[14];
    const float* lin_W  = (const float*)d_in[15];
    const float* lin_b  = (const float*)d_in[16];
    float* out = (float*)d_out;

    const int ngrid = (NN + 63) / 64;         // 1563
    const int egrid = NN / (2 * EW);          // 12500
    const int etg   = (ET + 255) / 256;
    const int pgrid = (NN + 255) / 256;

    hist_kernel<<<etg, 256>>>(ei);                                          // 0
    scanF_kernel<<<1, 1024>>>();                                            // 1
    scatter_gemm1_kernel<<<SCAT_BLOCKS + ngrid, 256>>>(ei, x, W1, a1s, a1d);// 2
    edge_csr_kernel<<<egrid, 128>>>();                                      // 3

    gemm_al_kernel<DD><<<ngrid, 256>>>(W2, a2s, a2d, b1);                   // 4
    edge_csr_kernel<<<egrid, 128>>>();                                      // 5

    gemm_al_kernel<DD><<<ngrid, 256>>>(W3, a3s, a3d, b2);                   // 6
    edge_csr_kernel<<<egrid, 128>>>();                                      // 7

    pool2_kernel<<<pgrid, 256>>>(batch, b3);                                // 8
    final_kernel<<<1, GG * NCLS>>>(lin_W, lin_b, out);                      // 9
}

// round 14
// speedup vs baseline: 1.0637x; 1.0637x over previous
#include <cuda_runtime.h>
#include <math.h>

#define NN   100000
#define EE   1600000
#define ET   (EE + NN)     // edges + self loops
#define FIN  128
#define DD   64
#define HH   8
#define GG   64
#define NCLS 10
#define SLOPE 0.2f

#define SCAT_BLOCKS ((ET + 255) / 256)   // 6641

// ---------------- scratch (device globals) ----------------
__device__ float g_proj[NN * DD];        // h = I @ W (fp32)
__device__ float g_act [NN * DD];        // normalized layer output
__device__ float g_als [NN * HH];
__device__ float g_ald [NN * HH];
__device__ int   g_rowptr[NN + 1];
__device__ int   g_col [ET];
__device__ int   g_cnti[NN];             // zero-init; re-zeroed by scatter tail
__device__ int   g_rank[ET];
__device__ float g_sums[GG * DD];        // zero-init; re-zeroed by final tail
__device__ float g_cnt [GG];

// ---------------- CSR build ----------------
__global__ void hist_kernel(const int* __restrict__ ei) {
    int i = blockIdx.x * blockDim.x + threadIdx.x;
    if (i >= ET) return;
    int dst = (i < EE) ? ei[EE + i] : (i - EE);
    g_rank[i] = atomicAdd(&g_cnti[dst], 1);
}

// Single-block fused exclusive scan of g_cnti -> g_rowptr.
__global__ void scanF_kernel() {
    __shared__ int wsum[32];
    __shared__ int woff[32];
    __shared__ int tot;
    const int t = threadIdx.x;
    const int lane = t & 31, wid = t >> 5;
    int run = 0;
    for (int chunk = 0; chunk < 98; chunk++) {
        int idx = chunk * 1024 + t;
        int v = (idx < NN) ? g_cnti[idx] : 0;
        int inc = v;
#pragma unroll
        for (int off = 1; off < 32; off <<= 1) {
            int x = __shfl_up_sync(0xffffffffu, inc, off);
            if (lane >= off) inc += x;
        }
        if (lane == 31) wsum[wid] = inc;
        __syncthreads();
        if (wid == 0) {
            int s = wsum[lane];
            int is = s;
#pragma unroll
            for (int off = 1; off < 32; off <<= 1) {
                int x = __shfl_up_sync(0xffffffffu, is, off);
                if (lane >= off) is += x;
            }
            woff[lane] = is - s;
            if (lane == 31) tot = is;
        }
        __syncthreads();
        if (idx < NN) g_rowptr[idx] = run + woff[wid] + (inc - v);
        run += tot;
    }
    if (t == 0) g_rowptr[NN] = run;
}

// ---------------- GEMM body: 64x64 tile, 4x4/thread, row-major xs (R11) -----
template<int K, bool FIRST>
__device__ __forceinline__ void gemm_body(int bid,
                                          const float* __restrict__ I,
                                          const float* __restrict__ W,
                                          const float* __restrict__ a_src,
                                          const float* __restrict__ a_dst,
                                          const float* __restrict__ prev_bias) {
    __shared__ float xs[64][68];
    __shared__ float Wsm[64][64];
    const int t  = threadIdx.x;
    const int tx = t & 15;
    const int ty = t >> 4;
    const int node0 = bid * 64;

    float acc[4][4];
#pragma unroll
    for (int i = 0; i < 4; i++)
#pragma unroll
        for (int j = 0; j < 4; j++) acc[i][j] = 0.f;

    for (int kc = 0; kc < K; kc += 64) {
        // stage xs: 64 nodes x 64 k (1024 float4, 4/thread)
#pragma unroll
        for (int it = 0; it < 4; it++) {
            int fid  = t + it * 256;
            int node = fid >> 4;
            int kq   = (fid & 15) * 4;
            int gn   = node0 + node;
            float4 v = make_float4(0.f, 0.f, 0.f, 0.f);
            if (gn < NN) {
                if (FIRST) {
                    v = *(const float4*)&I[(size_t)gn * K + kc + kq];
                } else {
                    v = *(const float4*)&g_act[(size_t)gn * K + kc + kq];
                    v.x += prev_bias[kc + kq    ];
                    v.y += prev_bias[kc + kq + 1];
                    v.z += prev_bias[kc + kq + 2];
                    v.w += prev_bias[kc + kq + 3];
                    v.x = v.x > 0.f ? v.x : expm1f(v.x);
                    v.y = v.y > 0.f ? v.y : expm1f(v.y);
                    v.z = v.z > 0.f ? v.z : expm1f(v.z);
                    v.w = v.w > 0.f ? v.w : expm1f(v.w);
                }
            }
            *(float4*)&xs[node][kq] = v;
        }
        // stage W chunk: 64 x 64 (1024 float4, 4/thread)
#pragma unroll
        for (int it = 0; it < 4; it++) {
            int fid = t + it * 256;
            int kk  = fid >> 4;
            int cq  = (fid & 15) * 4;
            *(float4*)&Wsm[kk][cq] = *(const float4*)&W[(size_t)(kc + kk) * DD + cq];
        }
        __syncthreads();
#pragma unroll
        for (int k = 0; k < 64; k++) {
            float4 wv = *(const float4*)&Wsm[k][tx * 4];
            float xv0 = xs[4 * ty    ][k];
            float xv1 = xs[4 * ty + 1][k];
            float xv2 = xs[4 * ty + 2][k];
            float xv3 = xs[4 * ty + 3][k];
            acc[0][0] = fmaf(xv0, wv.x, acc[0][0]);
            acc[0][1] = fmaf(xv0, wv.y, acc[0][1]);
            acc[0][2] = fmaf(xv0, wv.z, acc[0][2]);
            acc[0][3] = fmaf(xv0, wv.w, acc[0][3]);
            acc[1][0] = fmaf(xv1, wv.x, acc[1][0]);
            acc[1][1] = fmaf(xv1, wv.y, acc[1][1]);
            acc[1][2] = fmaf(xv1, wv.z, acc[1][2]);
            acc[1][3] = fmaf(xv1, wv.w, acc[1][3]);
            acc[2][0] = fmaf(xv2, wv.x, acc[2][0]);
            acc[2][1] = fmaf(xv2, wv.y, acc[2][1]);
            acc[2][2] = fmaf(xv2, wv.z, acc[2][2]);
            acc[2][3] = fmaf(xv2, wv.w, acc[2][3]);
            acc[3][0] = fmaf(xv3, wv.x, acc[3][0]);
            acc[3][1] = fmaf(xv3, wv.y, acc[3][1]);
            acc[3][2] = fmaf(xv3, wv.z, acc[3][2]);
            acc[3][3] = fmaf(xv3, wv.w, acc[3][3]);
        }
        __syncthreads();
    }

#pragma unroll
    for (int i = 0; i < 4; i++) {
        int gn = node0 + 4 * ty + i;
        if (gn < NN)
            *(float4*)&g_proj[(size_t)gn * DD + tx * 4] =
                make_float4(acc[i][0], acc[i][1], acc[i][2], acc[i][3]);
    }

    // attention logits: head tx>>1 (cols 8h..8h+7 split across tx, tx^1)
#pragma unroll
    for (int i = 0; i < 4; i++) {
        float s = 0.f, d = 0.f;
#pragma unroll
        for (int j = 0; j < 4; j++) {
            int c = tx * 4 + j;
            s = fmaf(acc[i][j], a_src[c], s);
            d = fmaf(acc[i][j], a_dst[c], d);
        }
        s += __shfl_xor_sync(0xffffffffu, s, 1);
        d += __shfl_xor_sync(0xffffffffu, d, 1);
        int gn = node0 + 4 * ty + i;
        if ((tx & 1) == 0 && gn < NN) {
            int h = tx >> 1;
            g_als[gn * HH + h] = s;
            g_ald[gn * HH + h] = d;
        }
    }
}

// ---------------- fused scatter + layer-1 GEMM ------------------------------
__global__ void scatter_gemm1_kernel(const int* __restrict__ ei,
                                     const float* __restrict__ x,
                                     const float* __restrict__ W1,
                                     const float* __restrict__ a1s,
                                     const float* __restrict__ a1d) {
    if (blockIdx.x < SCAT_BLOCKS) {
        int i = blockIdx.x * 256 + threadIdx.x;
        if (i < NN) g_cnti[i] = 0;
        if (i >= ET) return;
        int src, dst;
        if (i < EE) { src = ei[i]; dst = ei[EE + i]; }
        else        { src = dst = i - EE; }
        g_col[g_rowptr[dst] + g_rank[i]] = src;
    } else {
        gemm_body<FIN, true>(blockIdx.x - SCAT_BLOCKS, x, W1, a1s, a1d, nullptr);
    }
}

// ---------------- standalone GEMM (layers 2/3) ------------------------------
template<int K>
__global__ void gemm_al_kernel(const float* __restrict__ W,
                               const float* __restrict__ a_src,
                               const float* __restrict__ a_dst,
                               const float* __restrict__ prev_bias) {
    gemm_body<K, false>(blockIdx.x, nullptr, W, a_src, a_dst, prev_bias);
}

// ---------------- dual-dst CSR edge kernel (EW=4, split full/remainder) -----
#define EW 4
__global__ void __launch_bounds__(128) edge_csr_kernel() {
    __shared__ int   ss[EW][2][16];
    __shared__ float ws[EW][2][16][9];
    const int wl   = threadIdx.x >> 5;
    const int lane = threadIdx.x & 31;
    const int half = lane >> 4;
    const int l    = lane & 15;
    const int hh   = l >> 1;
    const int n = blockIdx.x * (2 * EW) + 2 * wl + half;   // NN%8==0: valid

    const int rs = g_rowptr[n], re = g_rowptr[n + 1];
    const int len  = re - rs;
    const int olen = __shfl_xor_sync(0xffffffffu, len, 16);
    const int mlen = max(len, olen);

    const float4 ad0 = *(const float4*)&g_ald[n * HH];
    const float4 ad1 = *(const float4*)&g_ald[n * HH + 4];

    float4 acc = make_float4(0.f, 0.f, 0.f, 0.f);
    float dn = 0.f;

    int base = 0;
    // full chunks: compile-time trip count 16 in the hot loop
    for (; base + 16 <= mlen; base += 16) {
        const int e = rs + base + l;
        const bool valid = (e < re);
        int src = valid ? g_col[e] : 0;
        ss[wl][half][l] = src;
        {
            float4 s0 = *(const float4*)&g_als[src * HH];
            float4 s1 = *(const float4*)&g_als[src * HH + 4];
            float ev[8] = { s0.x + ad0.x, s0.y + ad0.y, s0.z + ad0.z, s0.w + ad0.w,
                            s1.x + ad1.x, s1.y + ad1.y, s1.z + ad1.z, s1.w + ad1.w };
            const float m = valid ? 1.f : 0.f;
#pragma unroll
            for (int k = 0; k < 8; k++) {
                float v = ev[k] > 0.f ? ev[k] : SLOPE * ev[k];
                ws[wl][half][l][k] = m * __expf(v);
            }
        }
        __syncwarp();
#pragma unroll 4
        for (int j = 0; j < 16; j++) {
            int   sj = ss[wl][half][j];
            float wj = ws[wl][half][j][hh];
            dn += wj;
            float4 p = *(const float4*)&g_proj[(size_t)sj * DD + 4 * l];
            acc.x = fmaf(p.x, wj, acc.x);
            acc.y = fmaf(p.y, wj, acc.y);
            acc.z = fmaf(p.z, wj, acc.z);
            acc.w = fmaf(p.w, wj, acc.w);
        }
        __syncwarp();
    }
    // remainder chunk
    if (base < mlen) {
        const int e = rs + base + l;
        const bool valid = (e < re);
        int src = valid ? g_col[e] : 0;
        ss[wl][half][l] = src;
        {
            float4 s0 = *(const float4*)&g_als[src * HH];
            float4 s1 = *(const float4*)&g_als[src * HH + 4];
            float ev[8] = { s0.x + ad0.x, s0.y + ad0.y, s0.z + ad0.z, s0.w + ad0.w,
                            s1.x + ad1.x, s1.y + ad1.y, s1.z + ad1.z, s1.w + ad1.w };
            const float m = valid ? 1.f : 0.f;
#pragma unroll
            for (int k = 0; k < 8; k++) {
                float v = ev[k] > 0.f ? ev[k] : SLOPE * ev[k];
                ws[wl][half][l][k] = m * __expf(v);
            }
        }
        __syncwarp();
        const int cnt = mlen - base;
#pragma unroll 4
        for (int j = 0; j < cnt; j++) {
            int   sj = ss[wl][half][j];
            float wj = ws[wl][half][j][hh];
            dn += wj;
            float4 p = *(const float4*)&g_proj[(size_t)sj * DD + 4 * l];
            acc.x = fmaf(p.x, wj, acc.x);
            acc.y = fmaf(p.y, wj, acc.y);
            acc.z = fmaf(p.z, wj, acc.z);
            acc.w = fmaf(p.w, wj, acc.w);
        }
    }

    const float inv = 1.f / dn;
    *(float4*)&g_act[(size_t)n * DD + 4 * l] =
        make_float4(acc.x * inv, acc.y * inv, acc.z * inv, acc.w * inv);
}

// ---------------- hierarchical pool (flush-on-graph-change) ----------------
__global__ void pool2_kernel(const int* __restrict__ batch,
                             const float* __restrict__ b3) {
    const int t = threadIdx.x;          // 256
    const int d = t & 63;
    const int r = t >> 6;
    const int start = blockIdx.x * 256;
    const float bias = b3[d];
    int curg = -1;
    float accv = 0.f, accc = 0.f;
    for (int k = 0; k < 64; k++) {
        int n = start + r + k * 4;
        if (n >= NN) break;
        int g = batch[n];
        if (g != curg) {
            if (curg >= 0) {
                atomicAdd(&g_sums[curg * DD + d], accv);
                if (d == 0) atomicAdd(&g_cnt[curg], accc);
            }
            curg = g; accv = 0.f; accc = 0.f;
        }
        float v = g_act[(size_t)n * DD + d] + bias;
        v = v > 0.f ? v : expm1f(v);
        accv += v;
        accc += 1.f;
    }
    if (curg >= 0) {
        atomicAdd(&g_sums[curg * DD + d], accv);
        if (d == 0) atomicAdd(&g_cnt[curg], accc);
    }
}

// ---------------- final linear (+ re-zero pool buffers) ---------------------
__global__ void final_kernel(const float* __restrict__ lin_W,
                             const float* __restrict__ lin_b,
                             float* __restrict__ out) {
    int t = threadIdx.x;                // 640
    int g = t / NCLS;
    int c = t % NCLS;
    float cnt = fmaxf(g_cnt[g], 1.0f);
    float acc = lin_b[c];
#pragma unroll
    for (int d = 0; d < DD; d++)
        acc = fmaf(g_sums[g * DD + d] / cnt, lin_W[d * NCLS + c], acc);
    out[g * NCLS + c] = acc;
    __syncthreads();
    for (int i = t; i < GG * DD; i += 640) g_sums[i] = 0.f;
    if (t < GG) g_cnt[t] = 0.f;
}

// ---------------- launch ----------------
extern "C" void kernel_launch(void* const* d_in, const int* in_sizes, int n_in,
                              void* d_out, int out_size) {
    const float* x      = (const float*)d_in[0];
    const int*   ei     = (const int*)  d_in[1];
    const int*   batch  = (const int*)  d_in[2];
    const float* W1     = (const float*)d_in[3];
    const float* a1s    = (const float*)d_in[4];
    const float* a1d    = (const float*)d_in[5];
    const float* b1     = (const float*)d_in[6];
    const float* W2     = (const float*)d_in[7];
    const float* a2s    = (const float*)d_in[8];
    const float* a2d    = (const float*)d_in[9];
    const float* b2     = (const float*)d_in[10];
    const float* W3     = (const float*)d_in[11];
    const float* a3s    = (const float*)d_in[12];
    const float* a3d    = (const float*)d_in[13];
    const float* b3     = (const float*)d_in[14];
    const float* lin_W  = (const float*)d_in[15];
    const float* lin_b  = (const float*)d_in[16];
    float* out = (float*)d_out;

    const int ngrid = (NN + 63) / 64;         // 1563
    const int egrid = NN / (2 * EW);          // 12500
    const int etg   = (ET + 255) / 256;
    const int pgrid = (NN + 255) / 256;

    hist_kernel<<<etg, 256>>>(ei);                                          // 0
    scanF_kernel<<<1, 1024>>>();                                            // 1
    scatter_gemm1_kernel<<<SCAT_BLOCKS + ngrid, 256>>>(ei, x, W1, a1s, a1d);// 2
    edge_csr_kernel<<<egrid, 128>>>();                                      // 3

    gemm_al_kernel<DD><<<ngrid, 256>>>(W2, a2s, a2d, b1);                   // 4
    edge_csr_kernel<<<egrid, 128>>>();                                      // 5

    gemm_al_kernel<DD><<<ngrid, 256>>>(W3, a3s, a3d, b2);                   // 6
    edge_csr_kernel<<<egrid, 128>>>();                                      // 7

    pool2_kernel<<<pgrid, 256>>>(batch, b3);                                // 8
    final_kernel<<<1, GG * NCLS>>>(lin_W, lin_b, out);                      // 9
}

// round 16
// speedup vs baseline: 1.1327x; 1.0648x over previous
#include <cuda_runtime.h>
#include <math.h>

#define NN   100000
#define EE   1600000
#define ET   (EE + NN)     // edges + self loops
#define FIN  128
#define DD   64
#define HH   8
#define GG   64
#define NCLS 10
#define SLOPE 0.2f

#define HIST_BLOCKS ((ET + 255) / 256)   // 6641

// ---------------- scratch (device globals) ----------------
__device__ float g_proj[NN * DD];        // h = I @ W (fp32)
__device__ float g_act [NN * DD];        // normalized layer output
__device__ float g_als [NN * HH];
__device__ float g_ald [NN * HH];
__device__ int   g_rowptr[NN + 1];
__device__ int   g_col [ET];
__device__ int   g_cnti[NN];             // zero-init; re-zeroed by scatter tail
__device__ int   g_rank[ET];
__device__ float g_sums[GG * DD];        // zero-init; re-zeroed by final tail
__device__ float g_cnt [GG];

// ---------------- GEMM body: 64x64 tile, 4x4/thread, row-major xs -----------
template<int K, bool FIRST>
__device__ __forceinline__ void gemm_body(int bid,
                                          const float* __restrict__ I,
                                          const float* __restrict__ W,
                                          const float* __restrict__ a_src,
                                          const float* __restrict__ a_dst,
                                          const float* __restrict__ prev_bias) {
    __shared__ float xs[64][68];
    __shared__ float Wsm[64][64];
    const int t  = threadIdx.x;
    const int tx = t & 15;
    const int ty = t >> 4;
    const int node0 = bid * 64;

    float acc[4][4];
#pragma unroll
    for (int i = 0; i < 4; i++)
#pragma unroll
        for (int j = 0; j < 4; j++) acc[i][j] = 0.f;

    for (int kc = 0; kc < K; kc += 64) {
#pragma unroll
        for (int it = 0; it < 4; it++) {
            int fid  = t + it * 256;
            int node = fid >> 4;
            int kq   = (fid & 15) * 4;
            int gn   = node0 + node;
            float4 v = make_float4(0.f, 0.f, 0.f, 0.f);
            if (gn < NN) {
                if (FIRST) {
                    v = *(const float4*)&I[(size_t)gn * K + kc + kq];
                } else {
                    v = *(const float4*)&g_act[(size_t)gn * K + kc + kq];
                    v.x += prev_bias[kc + kq    ];
                    v.y += prev_bias[kc + kq + 1];
                    v.z += prev_bias[kc + kq + 2];
                    v.w += prev_bias[kc + kq + 3];
                    v.x = v.x > 0.f ? v.x : expm1f(v.x);
                    v.y = v.y > 0.f ? v.y : expm1f(v.y);
                    v.z = v.z > 0.f ? v.z : expm1f(v.z);
                    v.w = v.w > 0.f ? v.w : expm1f(v.w);
                }
            }
            *(float4*)&xs[node][kq] = v;
        }
#pragma unroll
        for (int it = 0; it < 4; it++) {
            int fid = t + it * 256;
            int kk  = fid >> 4;
            int cq  = (fid & 15) * 4;
            *(float4*)&Wsm[kk][cq] = *(const float4*)&W[(size_t)(kc + kk) * DD + cq];
        }
        __syncthreads();
#pragma unroll
        for (int k = 0; k < 64; k++) {
            float4 wv = *(const float4*)&Wsm[k][tx * 4];
            float xv0 = xs[4 * ty    ][k];
            float xv1 = xs[4 * ty + 1][k];
            float xv2 = xs[4 * ty + 2][k];
            float xv3 = xs[4 * ty + 3][k];
            acc[0][0] = fmaf(xv0, wv.x, acc[0][0]);
            acc[0][1] = fmaf(xv0, wv.y, acc[0][1]);
            acc[0][2] = fmaf(xv0, wv.z, acc[0][2]);
            acc[0][3] = fmaf(xv0, wv.w, acc[0][3]);
            acc[1][0] = fmaf(xv1, wv.x, acc[1][0]);
            acc[1][1] = fmaf(xv1, wv.y, acc[1][1]);
            acc[1][2] = fmaf(xv1, wv.z, acc[1][2]);
            acc[1][3] = fmaf(xv1, wv.w, acc[1][3]);
            acc[2][0] = fmaf(xv2, wv.x, acc[2][0]);
            acc[2][1] = fmaf(xv2, wv.y, acc[2][1]);
            acc[2][2] = fmaf(xv2, wv.z, acc[2][2]);
            acc[2][3] = fmaf(xv2, wv.w, acc[2][3]);
            acc[3][0] = fmaf(xv3, wv.x, acc[3][0]);
            acc[3][1] = fmaf(xv3, wv.y, acc[3][1]);
            acc[3][2] = fmaf(xv3, wv.z, acc[3][2]);
            acc[3][3] = fmaf(xv3, wv.w, acc[3][3]);
        }
        __syncthreads();
    }

#pragma unroll
    for (int i = 0; i < 4; i++) {
        int gn = node0 + 4 * ty + i;
        if (gn < NN)
            *(float4*)&g_proj[(size_t)gn * DD + tx * 4] =
                make_float4(acc[i][0], acc[i][1], acc[i][2], acc[i][3]);
    }

#pragma unroll
    for (int i = 0; i < 4; i++) {
        float s = 0.f, d = 0.f;
#pragma unroll
        for (int j = 0; j < 4; j++) {
            int c = tx * 4 + j;
            s = fmaf(acc[i][j], a_src[c], s);
            d = fmaf(acc[i][j], a_dst[c], d);
        }
        s += __shfl_xor_sync(0xffffffffu, s, 1);
        d += __shfl_xor_sync(0xffffffffu, d, 1);
        int gn = node0 + 4 * ty + i;
        if ((tx & 1) == 0 && gn < NN) {
            int h = tx >> 1;
            g_als[gn * HH + h] = s;
            g_ald[gn * HH + h] = d;
        }
    }
}

// ---------------- fused hist + layer-1 GEMM (both DAG entry nodes) ----------
__global__ void hist_gemm1_kernel(const int* __restrict__ ei,
                                  const float* __restrict__ x,
                                  const float* __restrict__ W1,
                                  const float* __restrict__ a1s,
                                  const float* __restrict__ a1d) {
    if (blockIdx.x < HIST_BLOCKS) {
        int i = blockIdx.x * 256 + threadIdx.x;
        if (i >= ET) return;
        int dst = (i < EE) ? ei[EE + i] : (i - EE);
        g_rank[i] = atomicAdd(&g_cnti[dst], 1);
    } else {
        gemm_body<FIN, true>(blockIdx.x - HIST_BLOCKS, x, W1, a1s, a1d, nullptr);
    }
}

// ---------------- scanF: software-pipelined single-block scan ---------------
// Prefetch chunk c+1's loads before processing chunk c (the only serial
// dependency is the running total).
__global__ void scanF_kernel() {
    __shared__ int wsum[32];
    __shared__ int woff[32];
    __shared__ int tot;
    const int t = threadIdx.x;
    const int lane = t & 31, wid = t >> 5;
    int run = 0;
    int v = (t < NN) ? g_cnti[t] : 0;       // chunk 0 load
    for (int chunk = 0; chunk < 98; chunk++) {
        // prefetch next chunk while this chunk's scan proceeds
        int nv = 0;
        if (chunk + 1 < 98) {
            int nidx = (chunk + 1) * 1024 + t;
            if (nidx < NN) nv = g_cnti[nidx];
        }
        int idx = chunk * 1024 + t;
        int inc = v;
#pragma unroll
        for (int off = 1; off < 32; off <<= 1) {
            int x = __shfl_up_sync(0xffffffffu, inc, off);
            if (lane >= off) inc += x;
        }
        if (lane == 31) wsum[wid] = inc;
        __syncthreads();
        if (wid == 0) {
            int s = wsum[lane];
            int is = s;
#pragma unroll
            for (int off = 1; off < 32; off <<= 1) {
                int x = __shfl_up_sync(0xffffffffu, is, off);
                if (lane >= off) is += x;
            }
            woff[lane] = is - s;
            if (lane == 31) tot = is;
        }
        __syncthreads();
        if (idx < NN) g_rowptr[idx] = run + woff[wid] + (inc - v);
        run += tot;
        v = nv;
    }
    if (t == 0) g_rowptr[NN] = run;
}

// ---------------- scatter (atomic-free via rank) ----------------------------
__global__ void scatter_kernel(const int* __restrict__ ei) {
    int i = blockIdx.x * blockDim.x + threadIdx.x;
    if (i < NN) g_cnti[i] = 0;            // re-zero for next replay
    if (i >= ET) return;
    int src, dst;
    if (i < EE) { src = ei[i]; dst = ei[EE + i]; }
    else        { src = dst = i - EE; }
    g_col[g_rowptr[dst] + g_rank[i]] = src;
}

// ---------------- standalone GEMM (layers 2/3) ------------------------------
template<int K>
__global__ void gemm_al_kernel(const float* __restrict__ W,
                               const float* __restrict__ a_src,
                               const float* __restrict__ a_dst,
                               const float* __restrict__ prev_bias) {
    gemm_body<K, false>(blockIdx.x, nullptr, W, a_src, a_dst, prev_bias);
}

// ---------------- dual-dst CSR edge kernel (EW=4, pre-scaled offsets) -------
#define EW 4
__global__ void __launch_bounds__(128) edge_csr_kernel() {
    __shared__ int   ss[EW][2][16];       // pre-scaled byte offsets src*256
    __shared__ float ws[EW][2][16][9];
    const int wl   = threadIdx.x >> 5;
    const int lane = threadIdx.x & 31;
    const int half = lane >> 4;
    const int l    = lane & 15;
    const int hh   = l >> 1;
    const int n = blockIdx.x * (2 * EW) + 2 * wl + half;

    const int rs = g_rowptr[n], re = g_rowptr[n + 1];
    const int len  = re - rs;
    const int olen = __shfl_xor_sync(0xffffffffu, len, 16);
    const int mlen = max(len, olen);

    const float4 ad0 = *(const float4*)&g_ald[n * HH];
    const float4 ad1 = *(const float4*)&g_ald[n * HH + 4];
    const char* const projb = (const char*)g_proj + (l << 4);

    float4 acc = make_float4(0.f, 0.f, 0.f, 0.f);
    float dn = 0.f;

    int base = 0;
    for (; base + 16 <= mlen; base += 16) {
        const int e = rs + base + l;
        const bool valid = (e < re);
        int src = valid ? g_col[e] : 0;
        ss[wl][half][l] = src * 256;      // byte offset of proj row
        {
            float4 s0 = *(const float4*)&g_als[src * HH];
            float4 s1 = *(const float4*)&g_als[src * HH + 4];
            float ev[8] = { s0.x + ad0.x, s0.y + ad0.y, s0.z + ad0.z, s0.w + ad0.w,
                            s1.x + ad1.x, s1.y + ad1.y, s1.z + ad1.z, s1.w + ad1.w };
            const float m = valid ? 1.f : 0.f;
#pragma unroll
            for (int k = 0; k < 8; k++) {
                float v = ev[k] > 0.f ? ev[k] : SLOPE * ev[k];
                ws[wl][half][l][k] = m * __expf(v);
            }
        }
        __syncwarp();
#pragma unroll 4
        for (int j = 0; j < 16; j++) {
            int   off = ss[wl][half][j];
            float wj  = ws[wl][half][j][hh];
            dn += wj;
            float4 p = *(const float4*)(projb + off);
            acc.x = fmaf(p.x, wj, acc.x);
            acc.y = fmaf(p.y, wj, acc.y);
            acc.z = fmaf(p.z, wj, acc.z);
            acc.w = fmaf(p.w, wj, acc.w);
        }
        __syncwarp();
    }
    if (base < mlen) {
        const int e = rs + base + l;
        const bool valid = (e < re);
        int src = valid ? g_col[e] : 0;
        ss[wl][half][l] = src * 256;
        {
            float4 s0 = *(const float4*)&g_als[src * HH];
            float4 s1 = *(const float4*)&g_als[src * HH + 4];
            float ev[8] = { s0.x + ad0.x, s0.y + ad0.y, s0.z + ad0.z, s0.w + ad0.w,
                            s1.x + ad1.x, s1.y + ad1.y, s1.z + ad1.z, s1.w + ad1.w };
            const float m = valid ? 1.f : 0.f;
#pragma unroll
            for (int k = 0; k < 8; k++) {
                float v = ev[k] > 0.f ? ev[k] : SLOPE * ev[k];
                ws[wl][half][l][k] = m * __expf(v);
            }
        }
        __syncwarp();
        const int cnt = mlen - base;
#pragma unroll 4
        for (int j = 0; j < cnt; j++) {
            int   off = ss[wl][half][j];
            float wj  = ws[wl][half][j][hh];
            dn += wj;
            float4 p = *(const float4*)(projb + off);
            acc.x = fmaf(p.x, wj, acc.x);
            acc.y = fmaf(p.y, wj, acc.y);
            acc.z = fmaf(p.z, wj, acc.z);
            acc.w = fmaf(p.w, wj, acc.w);
        }
    }

    const float inv = 1.f / dn;
    *(float4*)&g_act[(size_t)n * DD + 4 * l] =
        make_float4(acc.x * inv, acc.y * inv, acc.z * inv, acc.w * inv);
}

// ---------------- hierarchical pool (flush-on-graph-change) ----------------
__global__ void pool2_kernel(const int* __restrict__ batch,
                             const float* __restrict__ b3) {
    const int t = threadIdx.x;          // 256
    const int d = t & 63;
    const int r = t >> 6;
    const int start = blockIdx.x * 256;
    const float bias = b3[d];
    int curg = -1;
    float accv = 0.f, accc = 0.f;
    for (int k = 0; k < 64; k++) {
        int n = start + r + k * 4;
        if (n >= NN) break;
        int g = batch[n];
        if (g != curg) {
            if (curg >= 0) {
                atomicAdd(&g_sums[curg * DD + d], accv);
                if (d == 0) atomicAdd(&g_cnt[curg], accc);
            }
            curg = g; accv = 0.f; accc = 0.f;
        }
        float v = g_act[(size_t)n * DD + d] + bias;
        v = v > 0.f ? v : expm1f(v);
        accv += v;
        accc += 1.f;
    }
    if (curg >= 0) {
        atomicAdd(&g_sums[curg * DD + d], accv);
        if (d == 0) atomicAdd(&g_cnt[curg], accc);
    }
}

// ---------------- final linear (+ re-zero pool buffers) ---------------------
__global__ void final_kernel(const float* __restrict__ lin_W,
                             const float* __restrict__ lin_b,
                             float* __restrict__ out) {
    int t = threadIdx.x;                // 640
    int g = t / NCLS;
    int c = t % NCLS;
    float cnt = fmaxf(g_cnt[g], 1.0f);
    float acc = lin_b[c];
#pragma unroll
    for (int d = 0; d < DD; d++)
        acc = fmaf(g_sums[g * DD + d] / cnt, lin_W[d * NCLS + c], acc);
    out[g * NCLS + c] = acc;
    __syncthreads();
    for (int i = t; i < GG * DD; i += 640) g_sums[i] = 0.f;
    if (t < GG) g_cnt[t] = 0.f;
}

// ---------------- launch ----------------
extern "C" void kernel_launch(void* const* d_in, const int* in_sizes, int n_in,
                              void* d_out, int out_size) {
    const float* x      = (const float*)d_in[0];
    const int*   ei     = (const int*)  d_in[1];
    const int*   batch  = (const int*)  d_in[2];
    const float* W1     = (const float*)d_in[3];
    const float* a1s    = (const float*)d_in[4];
    const float* a1d    = (const float*)d_in[5];
    const float* b1     = (const float*)d_in[6];
    const float* W2     = (const float*)d_in[7];
    const float* a2s    = (const float*)d_in[8];
    const float* a2d    = (const float*)d_in[9];
    const float* b2     = (const float*)d_in[10];
    const float* W3     = (const float*)d_in[11];
    const float* a3s    = (const float*)d_in[12];
    const float* a3d    = (const float*)d_in[13];
    const float* b3     = (const float*)d_in[14];
    const float* lin_W  = (const float*)d_in[15];
    const float* lin_b  = (const float*)d_in[16];
    float* out = (float*)d_out;

    const int ngrid = (NN + 63) / 64;         // 1563
    const int egrid = NN / (2 * EW);          // 12500
    const int etg   = (ET + 255) / 256;
    const int pgrid = (NN + 255) / 256;

    hist_gemm1_kernel<<<HIST_BLOCKS + ngrid, 256>>>(ei, x, W1, a1s, a1d);   // 0
    scanF_kernel<<<1, 1024>>>();                                            // 1
    scatter_kernel<<<etg, 256>>>(ei);                                       // 2
    edge_csr_kernel<<<egrid, 128>>>();                                      // 3 (profiled)

    gemm_al_kernel<DD><<<ngrid, 256>>>(W2, a2s, a2d, b1);                   // 4
    edge_csr_kernel<<<egrid, 128>>>();                                      // 5

    gemm_al_kernel<DD><<<ngrid, 256>>>(W3, a3s, a3d, b2);                   // 6
    edge_csr_kernel<<<egrid, 128>>>();                                      // 7

    pool2_kernel<<<pgrid, 256>>>(batch, b3);                                // 8
    final_kernel<<<1, GG * NCLS>>>(lin_W, lin_b, out);                      // 9
}